// round 7
// baseline (speedup 1.0000x reference)
#include <cuda_runtime.h>
#include <cuda_bf16.h>
#include <cstdint>

#define NB 32
#define ND 64
#define NT 4096
#define NK 1024
#define NTOK (NB*NT)          // 131072 tokens
#define OUTQ (NB*ND*NT)       // 8388608 quantized elements

#define THREADS 512
#define CTA_TOK 256
#define TCHUNKS 5             // tensor: codes 0..639
#define FCHUNKS 3             // fma:    codes 640..1023
#define FBASE 640

#define CBSTRIDE 136          // ushorts per code row: [H(64)|M(64)|pad(8)] = 272B
#define TCHUNK_BYTES (128*CBSTRIDE*2)   // 34816
#define TCHUNK_16B (TCHUNK_BYTES/16)    // 2176
#define FCHUNK_BYTES (128*ND*4)         // 32768
#define FCHUNK_16B (FCHUNK_BYTES/16)    // 2048

#define SXS 260               // floats per dim row
// smem layout (bytes)
#define SMEM_SX   0                          // 64*260*4 = 66560
#define SMEM_TCB0 66560
#define SMEM_TCB1 (66560+34816)              // 101376
#define SMEM_FCB0 136192
#define SMEM_FCB1 (136192+32768)             // 168960
#define SMEM_TBV  201728                     // float[256]
#define SMEM_TSV  (201728+1024)
#define SMEM_TBI  (201728+2048)
#define SMEM_TSI  (201728+3072)
#define SMEM_SZ   (201728+4096)              // 205824

#define TAU 1e-3f
#define GT_TPB 256
#define NPART 2048

// Scratch (no allocations allowed)
__device__ int            g_idx[NTOK];
__device__ float          g_part[NPART];
__device__ unsigned short g_cb[NK * CBSTRIDE];

// ============================ helpers ============================
static __device__ __forceinline__ uint32_t smem_to_u32(const void* p) {
    uint32_t a;
    asm("{ .reg .u64 tmp; cvta.to.shared.u64 tmp, %1; cvt.u32.u64 %0, tmp; }" : "=r"(a) : "l"(p));
    return a;
}
static __device__ __forceinline__ void cp_async16(uint32_t dst, const void* src) {
    asm volatile("cp.async.cg.shared.global [%0], [%1], 16;" :: "r"(dst), "l"(src) : "memory");
}
static __device__ __forceinline__ void cp_commit() {
    asm volatile("cp.async.commit_group;" ::: "memory");
}
static __device__ __forceinline__ void cp_wait1() {
    asm volatile("cp.async.wait_group 1;" ::: "memory");
}
static __device__ __forceinline__ void cp_wait0() {
    asm volatile("cp.async.wait_group 0;" ::: "memory");
}
static __device__ __forceinline__ void bar_sync(int id) {
    asm volatile("bar.sync %0, 256;" :: "r"(id) : "memory");
}
static __device__ __forceinline__ void ldmatrix_x4(uint32_t& r0, uint32_t& r1,
                                                   uint32_t& r2, uint32_t& r3, uint32_t a) {
    asm volatile("ldmatrix.sync.aligned.m8n8.x4.shared.b16 {%0,%1,%2,%3}, [%4];"
        : "=r"(r0), "=r"(r1), "=r"(r2), "=r"(r3) : "r"(a));
}
static __device__ __forceinline__ void mma_bf16(float* c,
                                                uint32_t a0, uint32_t a1, uint32_t a2, uint32_t a3,
                                                uint32_t b0, uint32_t b1) {
    asm volatile("mma.sync.aligned.m16n8k16.row.col.f32.bf16.bf16.f32 "
        "{%0,%1,%2,%3}, {%4,%5,%6,%7}, {%8,%9}, {%0,%1,%2,%3};"
        : "+f"(c[0]), "+f"(c[1]), "+f"(c[2]), "+f"(c[3])
        : "r"(a0), "r"(a1), "r"(a2), "r"(a3), "r"(b0), "r"(b1));
}
static __device__ __forceinline__ uint32_t packbf(__nv_bfloat16 a, __nv_bfloat16 b) {
    return (uint32_t)__bfloat16_as_ushort(a) | ((uint32_t)__bfloat16_as_ushort(b) << 16);
}
static __device__ __forceinline__ unsigned long long pack2(float lo, float hi) {
    unsigned long long r;
    asm("mov.b64 %0, {%1, %2};" : "=l"(r) : "f"(lo), "f"(hi));
    return r;
}
static __device__ __forceinline__ float2 unpack2(unsigned long long v) {
    float2 f;
    asm("mov.b64 {%0, %1}, %2;" : "=f"(f.x), "=f"(f.y) : "l"(v));
    return f;
}
static __device__ __forceinline__ void ffma2(unsigned long long &acc,
                                             unsigned long long a, unsigned long long b) {
    asm("fma.rn.f32x2 %0, %1, %2, %3;" : "=l"(acc) : "l"(a), "l"(b), "l"(acc));
}
static __device__ __forceinline__ unsigned long long fadd2(unsigned long long a,
                                                           unsigned long long b) {
    unsigned long long r;
    asm("add.rn.f32x2 %0, %1, %2;" : "=l"(r) : "l"(a), "l"(b));
    return r;
}
static __device__ __forceinline__ void upd(float v, int idx, float& b, int& bi,
                                           float& s, int& si) {
    if (v > s) {
        if (v > b) { s = b; si = bi; b = v; bi = idx; }
        else       { s = v; si = idx; }
    }
}
static __device__ __forceinline__ void mrg(float& b, int& bi, float& s, int& si,
                                           float ob, int obi, float os, int osi) {
    if (ob > b || (ob == b && obi < bi)) {
        if (b > os || (b == os && bi < osi)) { s = b;  si = bi; }
        else                                 { s = os; si = osi; }
        b = ob; bi = obi;
    } else if (ob > s || (ob == s && obi < si)) {
        s = ob; si = obi;
    }
}

// ---------------------------------------------------------------------------
// Kernel 0: split codebook rows into [H | M] bf16, padded stride.
// ---------------------------------------------------------------------------
__global__ void vq_prep_kernel(const float* __restrict__ emb)
{
    int i = blockIdx.x * blockDim.x + threadIdx.x;
    if (i >= NK * ND) return;
    int code = i >> 6, d = i & 63;
    float v = emb[i];
    __nv_bfloat16 h = __float2bfloat16_rn(v);
    __nv_bfloat16 m = __float2bfloat16_rn(v - __bfloat162float(h));
    g_cb[code * CBSTRIDE + d]      = __bfloat16_as_ushort(h);
    g_cb[code * CBSTRIDE + 64 + d] = __bfloat16_as_ushort(m);
}

// ---------------------------------------------------------------------------
// Kernel 1: hybrid warp-specialized argmax. CTA = 256 tokens, 512 threads.
// Warps 0-7 : HMMA bf16 3-product path, codes 0..639   (tensor pipe)
// Warps 8-15: f32x2 FFMA path,          codes 640..1023 (fma pipe)
// Both run concurrently on different pipes; top-2 merged via smem; near-ties
// (margin < TAU) -> warp-cooperative exact fp32 rescan of ALL 1024 codes.
// ---------------------------------------------------------------------------
__global__ void __launch_bounds__(THREADS, 1) vq_hybrid_argmax_kernel(
        const float* __restrict__ in, const float* __restrict__ emb,
        float* __restrict__ out)
{
    extern __shared__ char smem[];
    float* sx = reinterpret_cast<float*>(smem);
    const uint32_t sbase = smem_to_u32(smem);
    const int tid  = threadIdx.x;
    const int lane = tid & 31;
    const int wid  = tid >> 5;

    const int n0 = blockIdx.x * CTA_TOK;
    const int b  = n0 >> 12;
    const int t0 = n0 & (NT - 1);

    // ---- preload first chunk of each stream (own group only) ----
    if (wid < 8) {
        for (int i = tid; i < TCHUNK_16B; i += 256)
            cp_async16(sbase + SMEM_TCB0 + i * 16, (const char*)g_cb + i * 16);
        cp_commit();
    } else {
        const char* src = (const char*)(emb + (size_t)FBASE * ND);
        for (int i = tid - 256; i < FCHUNK_16B; i += 256)
            cp_async16(sbase + SMEM_FCB0 + i * 16, src + i * 16);
        cp_commit();
    }

    // ---- stage x tile [64 d][256 t] fp32, all 512 threads ----
    {
        const float4* src = reinterpret_cast<const float4*>(in + (size_t)b * ND * NT + t0);
#pragma unroll
        for (int k = 0; k < 8; k++) {
            int i = tid + k * THREADS;
            int d = i >> 6, q = i & 63;
            float4 v = src[(size_t)d * (NT / 4) + q];
            *reinterpret_cast<float4*>(sx + d * SXS + q * 4) = v;
        }
    }
    __syncthreads();   // sx visible to everyone

    if (wid < 8) {
        // =================== TENSOR PATH (codes 0..639) ===================
        const int gid = lane >> 2;
        const int tig = lane & 3;
        const uint32_t lmoff = (uint32_t)((lane & 15) * (CBSTRIDE * 2) + ((lane >> 4) * 16));

        float bestv[4][2], secv[4][2];
        int   besti[4][2], seci[4][2];
#pragma unroll
        for (int g = 0; g < 4; g++)
#pragma unroll
            for (int col = 0; col < 2; col++) {
                bestv[g][col] = -3.0e38f; secv[g][col] = -3.0e38f;
                besti[g][col] = 0; seci[g][col] = 0;
            }

        for (int c = 0; c < TCHUNKS; c++) {
            if (c + 1 < TCHUNKS) {
                const uint32_t nb = (c & 1) ? SMEM_TCB0 : SMEM_TCB1;
                const char* src = (const char*)g_cb + (size_t)(c + 1) * TCHUNK_BYTES;
                for (int i = tid; i < TCHUNK_16B; i += 256)
                    cp_async16(sbase + nb + i * 16, src + i * 16);
                cp_commit();
                cp_wait1();
            } else {
                cp_wait0();
            }
            bar_sync(1);

            const uint32_t bufo = (c & 1) ? SMEM_TCB1 : SMEM_TCB0;
#pragma unroll
            for (int g = 0; g < 4; g++) {
                // rebuild token fragments for group g
                const int tok = wid * 32 + g * 8 + gid;
                uint32_t bh[8], bm[8];
#pragma unroll
                for (int j = 0; j < 4; j++) {
                    int d0 = j * 16 + 2 * tig;
                    float v0 = sx[d0 * SXS + tok];
                    float v1 = sx[(d0 + 1) * SXS + tok];
                    float v2 = sx[(d0 + 8) * SXS + tok];
                    float v3 = sx[(d0 + 9) * SXS + tok];
                    __nv_bfloat16 h0 = __float2bfloat16_rn(v0), h1 = __float2bfloat16_rn(v1);
                    __nv_bfloat16 h2 = __float2bfloat16_rn(v2), h3 = __float2bfloat16_rn(v3);
                    bh[2*j]   = packbf(h0, h1);
                    bh[2*j+1] = packbf(h2, h3);
                    bm[2*j]   = packbf(__float2bfloat16_rn(v0 - __bfloat162float(h0)),
                                       __float2bfloat16_rn(v1 - __bfloat162float(h1)));
                    bm[2*j+1] = packbf(__float2bfloat16_rn(v2 - __bfloat162float(h2)),
                                       __float2bfloat16_rn(v3 - __bfloat162float(h3)));
                }
#pragma unroll 2
                for (int mt = 0; mt < 8; mt++) {
                    uint32_t lm = sbase + bufo + lmoff + (uint32_t)(mt * 16 * CBSTRIDE * 2);
                    uint32_t AH[16], AM[16];
#pragma unroll
                    for (int jj = 0; jj < 4; jj++) {
                        ldmatrix_x4(AH[4*jj], AH[4*jj+1], AH[4*jj+2], AH[4*jj+3], lm + jj * 32);
                        ldmatrix_x4(AM[4*jj], AM[4*jj+1], AM[4*jj+2], AM[4*jj+3], lm + 128 + jj * 32);
                    }
                    // 3 independent chains (hH, hM, mH), interleaved
                    float p[4] = {0,0,0,0}, q[4] = {0,0,0,0}, r[4] = {0,0,0,0};
#pragma unroll
                    for (int jj = 0; jj < 4; jj++) {
                        mma_bf16(p, AH[4*jj], AH[4*jj+1], AH[4*jj+2], AH[4*jj+3], bh[2*jj], bh[2*jj+1]);
                        mma_bf16(q, AM[4*jj], AM[4*jj+1], AM[4*jj+2], AM[4*jj+3], bh[2*jj], bh[2*jj+1]);
                        mma_bf16(r, AH[4*jj], AH[4*jj+1], AH[4*jj+2], AH[4*jj+3], bm[2*jj], bm[2*jj+1]);
                    }
                    const int ib = c * 128 + mt * 16;
                    float f0 = p[0] + q[0] + r[0];
                    float f1 = p[1] + q[1] + r[1];
                    float f2 = p[2] + q[2] + r[2];
                    float f3 = p[3] + q[3] + r[3];
                    upd(f0, ib + gid,     bestv[g][0], besti[g][0], secv[g][0], seci[g][0]);
                    upd(f1, ib + gid,     bestv[g][1], besti[g][1], secv[g][1], seci[g][1]);
                    upd(f2, ib + gid + 8, bestv[g][0], besti[g][0], secv[g][0], seci[g][0]);
                    upd(f3, ib + gid + 8, bestv[g][1], besti[g][1], secv[g][1], seci[g][1]);
                }
            }
            bar_sync(1);   // all done with this buffer before it is overwritten
        }

        // butterfly merge across gid lanes; write per-token top2 to smem
        float* sbv = reinterpret_cast<float*>(smem + SMEM_TBV);
        float* ssv = reinterpret_cast<float*>(smem + SMEM_TSV);
        int*   sbi = reinterpret_cast<int*>(smem + SMEM_TBI);
        int*   ssi = reinterpret_cast<int*>(smem + SMEM_TSI);
#pragma unroll
        for (int g = 0; g < 4; g++) {
#pragma unroll
            for (int off = 4; off <= 16; off <<= 1)
#pragma unroll
                for (int col = 0; col < 2; col++) {
                    float ob  = __shfl_xor_sync(0xffffffffu, bestv[g][col], off);
                    int   obi = __shfl_xor_sync(0xffffffffu, besti[g][col], off);
                    float os  = __shfl_xor_sync(0xffffffffu, secv[g][col],  off);
                    int   osi = __shfl_xor_sync(0xffffffffu, seci[g][col],  off);
                    mrg(bestv[g][col], besti[g][col], secv[g][col], seci[g][col], ob, obi, os, osi);
                }
            if (lane < 4) {
                int tk = wid * 32 + g * 8 + 2 * lane;
                sbv[tk] = bestv[g][0]; ssv[tk] = secv[g][0];
                sbi[tk] = besti[g][0]; ssi[tk] = seci[g][0];
                sbv[tk+1] = bestv[g][1]; ssv[tk+1] = secv[g][1];
                sbi[tk+1] = besti[g][1]; ssi[tk+1] = seci[g][1];
            }
        }
        __syncthreads();   // publish tensor top2; fma finalizes
    } else {
        // ==================== FMA PATH (codes 640..1023) ====================
        const int tok = tid - 256;            // 0..255
        unsigned long long xp[32];
#pragma unroll
        for (int j = 0; j < 32; j++)
            xp[j] = pack2(sx[(2*j) * SXS + tok], sx[(2*j+1) * SXS + tok]);

        float best = -3.0e38f, sec = -3.0e38f;
        int   bi = 0, si = 0;

        for (int c = 0; c < FCHUNKS; c++) {
            if (c + 1 < FCHUNKS) {
                const uint32_t nb = (c & 1) ? SMEM_FCB0 : SMEM_FCB1;
                const char* src = (const char*)(emb + (size_t)(FBASE + (c + 1) * 128) * ND);
                for (int i = tid - 256; i < FCHUNK_16B; i += 256)
                    cp_async16(sbase + nb + i * 16, src + i * 16);
                cp_commit();
                cp_wait1();
            } else {
                cp_wait0();
            }
            bar_sync(2);

            const char* fbuf = smem + ((c & 1) ? SMEM_FCB1 : SMEM_FCB0);
            const int cb0 = FBASE + c * 128;
#pragma unroll 2
            for (int k = 0; k < 128; k++) {
                const ulonglong2* row = reinterpret_cast<const ulonglong2*>(fbuf + k * 256);
                unsigned long long a0 = 0ull, a1 = 0ull, a2 = 0ull, a3 = 0ull;
#pragma unroll
                for (int j = 0; j < 8; j++) {
                    ulonglong2 e0 = row[2*j];
                    ulonglong2 e1 = row[2*j + 1];
                    ffma2(a0, xp[4*j + 0], e0.x);
                    ffma2(a1, xp[4*j + 1], e0.y);
                    ffma2(a2, xp[4*j + 2], e1.x);
                    ffma2(a3, xp[4*j + 3], e1.y);
                }
                unsigned long long s2 = fadd2(fadd2(a0, a1), fadd2(a2, a3));
                float2 f = unpack2(s2);
                upd(f.x + f.y, cb0 + k, best, bi, sec, si);
            }
            bar_sync(2);
        }

        __syncthreads();   // tensor top2 published

        // merge with tensor-side top2
        {
            const float* sbv = reinterpret_cast<const float*>(smem + SMEM_TBV);
            const float* ssv = reinterpret_cast<const float*>(smem + SMEM_TSV);
            const int*   sbi = reinterpret_cast<const int*>(smem + SMEM_TBI);
            const int*   ssi = reinterpret_cast<const int*>(smem + SMEM_TSI);
            mrg(best, bi, sec, si, sbv[tok], sbi[tok], ssv[tok], ssi[tok]);
        }

        // near-tie rescue: exact fp32 rescan of ALL codes, warp-cooperative
        unsigned need = __ballot_sync(0xffffffffu, best - sec < TAU);
        while (need) {
            int l = __ffs(need) - 1;
            need &= need - 1;
            int ts = __shfl_sync(0xffffffffu, tok, l);
            float bb = -3.0e38f; int bbi = 0;
            for (int cc = lane; cc < NK; cc += 32) {
                const float* e = emb + (size_t)cc * ND;
                float a0 = 0.f, a1 = 0.f, a2 = 0.f, a3 = 0.f;
#pragma unroll
                for (int d = 0; d < ND; d += 4) {
                    a0 = fmaf(sx[d * SXS + ts],       e[d],     a0);
                    a1 = fmaf(sx[(d + 1) * SXS + ts], e[d + 1], a1);
                    a2 = fmaf(sx[(d + 2) * SXS + ts], e[d + 2], a2);
                    a3 = fmaf(sx[(d + 3) * SXS + ts], e[d + 3], a3);
                }
                float v = (a0 + a1) + (a2 + a3);
                if (v > bb) { bb = v; bbi = cc; }
            }
#pragma unroll
            for (int off = 16; off; off >>= 1) {
                float ov = __shfl_xor_sync(0xffffffffu, bb, off);
                int   oi = __shfl_xor_sync(0xffffffffu, bbi, off);
                if (ov > bb || (ov == bb && oi < bbi)) { bb = ov; bbi = oi; }
            }
            if (lane == l) bi = bbi;
        }

        const int n = n0 + tok;
        g_idx[n] = bi;
        out[OUTQ + 2 + n] = (float)bi;
    }
}

// ---------------------------------------------------------------------------
// Kernel 2: gather quantized output + loss partials (coalesced, smem-staged).
// commitment_loss == codebook_loss forward == mean((flat - emb_unnorm[idx])^2)
// ---------------------------------------------------------------------------
__global__ void __launch_bounds__(GT_TPB) vq_gather_loss_kernel(
        const float* __restrict__ in, const float* __restrict__ emb,
        const float* __restrict__ embu, float* __restrict__ out)
{
    __shared__ int   sidx[64];
    __shared__ float sq[64 * 65];
    __shared__ float su[64 * 65];

    const int tid = threadIdx.x;
    const int n0  = blockIdx.x * 64;
    const int b   = n0 >> 12;
    const int t0  = n0 & (NT - 1);

    if (tid < 64) sidx[tid] = g_idx[n0 + tid];
    __syncthreads();

    {
        const int tok = tid >> 2;
        const int q   = tid & 3;
        const int code = sidx[tok];
        const float4* e4 = reinterpret_cast<const float4*>(emb  + (size_t)code * ND);
        const float4* u4 = reinterpret_cast<const float4*>(embu + (size_t)code * ND);
#pragma unroll
        for (int j = 0; j < 4; j++) {
            float4 f = e4[q * 4 + j];
            float4 u = u4[q * 4 + j];
            int base = tok * 65 + q * 16 + j * 4;
            sq[base] = f.x; sq[base+1] = f.y; sq[base+2] = f.z; sq[base+3] = f.w;
            su[base] = u.x; su[base+1] = u.y; su[base+2] = u.z; su[base+3] = u.w;
        }
    }
    __syncthreads();

    const int d  = tid >> 2;
    const int j0 = (tid & 3) * 16;
    const size_t gbase = (size_t)b * ND * NT + (size_t)d * NT + t0 + j0;
    float lsum = 0.f;
#pragma unroll
    for (int i = 0; i < 16; i++) {
        float xi = in[gbase + i];
        out[gbase + i] = sq[(j0 + i) * 65 + d];
        float df = xi - su[(j0 + i) * 65 + d];
        lsum += df * df;
    }

#pragma unroll
    for (int o = 16; o; o >>= 1) lsum += __shfl_xor_sync(0xffffffffu, lsum, o);
    __shared__ float ws[GT_TPB / 32];
    if ((tid & 31) == 0) ws[tid >> 5] = lsum;
    __syncthreads();
    if (tid < 32) {
        float v = (tid < GT_TPB / 32) ? ws[tid] : 0.f;
#pragma unroll
        for (int o = 4; o; o >>= 1) v += __shfl_xor_sync(0xffffffffu, v, o);
        if (tid == 0) g_part[blockIdx.x] = v;
    }
}

// ---------------------------------------------------------------------------
// Kernel 3: final loss reduction (double precision), write scalars.
// ---------------------------------------------------------------------------
__global__ void vq_finalize_kernel(float* __restrict__ out)
{
    __shared__ double sd[256];
    double s = 0.0;
    for (int i = threadIdx.x; i < NPART; i += 256) s += (double)g_part[i];
    sd[threadIdx.x] = s;
    __syncthreads();
    for (int o = 128; o; o >>= 1) {
        if (threadIdx.x < o) sd[threadIdx.x] += sd[threadIdx.x + o];
        __syncthreads();
    }
    if (threadIdx.x == 0) {
        float m = (float)(sd[0] / (double)OUTQ);
        out[OUTQ]     = m;   // commitment_loss
        out[OUTQ + 1] = m;   // codebook_loss (numerically identical forward)
    }
}

extern "C" void kernel_launch(void* const* d_in, const int* in_sizes, int n_in,
                              void* d_out, int out_size) {
    const float* in   = (const float*)d_in[0];   // [32, 64, 4096] fp32
    const float* emb  = (const float*)d_in[1];   // [1024, 64] fp32 (pre-normalized)
    const float* embu = (const float*)d_in[2];   // [1024, 64] fp32
    float* out = (float*)d_out;

    static int configured = 0;
    if (!configured) {
        cudaFuncSetAttribute(vq_hybrid_argmax_kernel,
                             cudaFuncAttributeMaxDynamicSharedMemorySize, SMEM_SZ);
        configured = 1;
    }

    vq_prep_kernel<<<(NK * ND) / 256, 256>>>(emb);
    vq_hybrid_argmax_kernel<<<NTOK / CTA_TOK, THREADS, SMEM_SZ>>>(in, emb, out);
    vq_gather_loss_kernel<<<NPART, GT_TPB>>>(in, emb, embu, out);
    vq_finalize_kernel<<<1, 256>>>(out);
}